// round 9
// baseline (speedup 1.0000x reference)
#include <cuda_runtime.h>
#include <math.h>

#define T_DIM 512
#define B_DIM 1024
#define V_DIM 96
#define L_DIM 48
#define PKW   50          // packed row: 48 label probs + blank + pad (200 B)
#define CHUNK 16          // timesteps per cp.async chunk (3200 B contiguous)
#define NCH   4           // ring depth (chunks)
#define NCHUNKS (T_DIM / CHUNK)   // 32

// scratch (no cudaMalloc allowed). Layout: g_pk[b][t][PKW] so per-b rows are
// contiguous in t (one chunk = CHUNK*PKW floats = 3200 B, 16 B aligned).
__device__ float  g_pk[(size_t)B_DIM * T_DIM * PKW];   // ~105 MB
__device__ double g_loss[B_DIM];

// ---------------------------------------------------------------------------
// Kernel G: fused logsumexp + gather + normalize.
// One warp per (t,b) row (r = t*B+b). Writes 49 normalized probs to
// g_pk[(b*T + t)*PKW]: float2 (labels 2l,2l+1) per lane<24, blank at +48.
// ---------------------------------------------------------------------------
__global__ void __launch_bounds__(256) gather_kernel(const float* __restrict__ y_pred,
                                                     const int*   __restrict__ y_true) {
    int r    = (blockIdx.x * blockDim.x + threadIdx.x) >> 5;  // row id, grid exact
    int lane = threadIdx.x & 31;
    int t = r >> 10;             // r / B_DIM
    int b = r & (B_DIM - 1);

    const float* row = y_pred + (size_t)r * V_DIM;
    float x0 = row[lane];
    float x1 = row[lane + 32];
    float x2 = row[lane + 64];

    float m = fmaxf(x0, fmaxf(x1, x2));
    #pragma unroll
    for (int o = 16; o; o >>= 1) m = fmaxf(m, __shfl_xor_sync(0xFFFFFFFFu, m, o));
    float s = __expf(x0 - m) + __expf(x1 - m) + __expf(x2 - m);
    #pragma unroll
    for (int o = 16; o; o >>= 1) s += __shfl_xor_sync(0xFFFFFFFFu, s, o);
    float inv = __fdividef(1.0f, s);

    float* out = g_pk + ((size_t)b * T_DIM + t) * PKW;
    if (lane < 24) {
        int2 lp = *(const int2*)(y_true + b * L_DIM + 2 * lane);
        float p0 = __expf(row[lp.x] - m) * inv;   // L1 hits
        float p1 = __expf(row[lp.y] - m) * inv;
        *(float2*)(out + 2 * lane) = make_float2(p0, p1);
    } else if (lane == 24) {
        out[48] = __expf(row[0] - m) * inv;       // blank
    }
}

// ---------------------------------------------------------------------------
// Kernel B: CTC forward recursion on normalized probs, warp per batch element.
// Lane l owns states 4l..4l+3 in registers; one __shfl_up per step.
// Probs arrive via a cp.async (LDGSTS) pipelined smem ring: NCH=4 chunks of
// CHUNK=16 timesteps, NCH-2 chunks always in flight (lead ~= 32 steps).
// Completion via commit_group/wait_group -- no LDG scoreboard-slot aliasing,
// so the prefetch depth is guaranteed, unlike a register queue.
// FP64 alphas; exact power-of-2 rescale (recenter 2^440) every 16 steps.
// ---------------------------------------------------------------------------
#define NWARP 2   // warps (batch elements) per block
__global__ void __launch_bounds__(64) ctc_forward(const int* __restrict__ y_true) {
    __shared__ __align__(16) float ring[NWARP][NCH][CHUNK * PKW];  // 25.6 KB

    const int wib = threadIdx.x >> 5;
    const int b   = blockIdx.x * NWARP + wib;
    const int l   = threadIdx.x & 31;

    // skip-transition predicates
    int lab0 = 0, lab1 = 0;
    if (l < 24) {
        int2 lp = *(const int2*)(y_true + b * L_DIM + 2 * l);
        lab0 = lp.x; lab1 = lp.y;
    }
    int prevlab1 = __shfl_up_sync(0xFFFFFFFFu, lab1, 1);
    const double skip1d = (l >= 1 && l < 24 && lab0 != prevlab1) ? 1.0 : 0.0;
    const double skip3d = (l < 24 && lab1 != lab0) ? 1.0 : 0.0;
    const int off2 = (l < 24) ? 2 * l : 0;

    const float* src = g_pk + (size_t)b * T_DIM * PKW;

    // issue one chunk copy: 200 x 16B cp.async, one commit_group
    #define ISSUE(c_)                                                          \
    {                                                                          \
        const float* gsrc = src + (size_t)(c_) * (CHUNK * PKW);                \
        float* sdst = &ring[wib][(c_) & (NCH - 1)][0];                         \
        for (int i = l; i < (CHUNK * PKW) / 4; i += 32) {                      \
            unsigned sa = (unsigned)__cvta_generic_to_shared(sdst + 4 * i);    \
            asm volatile("cp.async.ca.shared.global [%0], [%1], 16;"           \
                         :: "r"(sa), "l"(gsrc + 4 * i));                       \
        }                                                                      \
        asm volatile("cp.async.commit_group;" ::: "memory");                   \
    }

    // prologue: chunks 0..NCH-2 in flight
    ISSUE(0); ISSUE(1); ISSUE(2);

    double a0 = 0.0, a1 = 0.0, a2 = 0.0, a3 = 0.0;
    int acc_k = 0;

    #define STEP(j, p01, pb)                                                   \
    {                                                                          \
        double pbd = (double)(pb);                                             \
        double p0d = (double)(p01).x;                                          \
        double p1d = (double)(p01).y;                                          \
        double sh3 = __shfl_up_sync(0xFFFFFFFFu, a3, 1);                       \
        if (l == 0) sh3 = 0.0;                                                 \
        double n0 = (a0 + sh3) * pbd;                                          \
        double n1 = (a0 + a1 + skip1d * sh3) * p0d;                            \
        double n2 = (a1 + a2) * pbd;                                           \
        double n3 = (a2 + a3 + skip3d * a1) * p1d;                             \
        if (l >= 24) { n1 = 0.0; n2 = 0.0; n3 = 0.0; }                         \
        if (l >  24) { n0 = 0.0; }                                             \
        a0 = n0; a1 = n1; a2 = n2; a3 = n3;                                    \
        if ((j) == CHUNK - 1) {                                                \
            double v = fmax(fmax(a0, a1), fmax(a2, a3));                       \
            _Pragma("unroll")                                                  \
            for (int o = 16; o; o >>= 1)                                       \
                v = fmax(v, __shfl_xor_sync(0xFFFFFFFFu, v, o));               \
            int eb = (__double2hiint(v) >> 20) & 0x7FF;                        \
            int shift = (1023 + 440) - eb;                                     \
            if (shift >  1020) shift =  1020;                                  \
            if (shift < -1020) shift = -1020;                                  \
            double scale = __hiloint2double((1023 + shift) << 20, 0);          \
            a0 *= scale; a1 *= scale; a2 *= scale; a3 *= scale;                \
            acc_k += shift;                                                    \
        }                                                                      \
    }

    for (int c = 0; c < NCHUNKS; c++) {
        // wait until chunk c's group has completed (groups retire in order)
        int n = NCHUNKS - 1 - c; if (n > NCH - 2) n = NCH - 2;
        if      (n == 2) asm volatile("cp.async.wait_group 2;" ::: "memory");
        else if (n == 1) asm volatile("cp.async.wait_group 1;" ::: "memory");
        else             asm volatile("cp.async.wait_group 0;" ::: "memory");
        __syncwarp();
        if (c + NCH - 1 < NCHUNKS) ISSUE(c + NCH - 1);

        const float* pk = &ring[wib][c & (NCH - 1)][0];
        #pragma unroll
        for (int j = 0; j < CHUNK; j++) {
            const float* prow = pk + j * PKW;
            float2 p01 = *(const float2*)(prow + off2);
            float  pb  = prow[48];
            if (c == 0 && j == 0) {   // t = 0 init: states 0,1 on lane 0
                if (l == 0) { a0 = (double)pb; a1 = (double)p01.x; }
                continue;
            }
            STEP(j, p01, pb);
        }
        __syncwarp();   // all lanes done reading slot before it is re-issued
    }
    #undef STEP
    #undef ISSUE

    // terminal states: s=95 (lane 23, a3) and s=96 (lane 24, a0)
    double v95 = __shfl_sync(0xFFFFFFFFu, a3, 23);
    double v96 = __shfl_sync(0xFFFFFFFFu, a0, 24);
    if (l == 0) {
        g_loss[b] = -log(v95 + v96) + (double)acc_k * 0.6931471805599453094;
    }
}

// ---------------------------------------------------------------------------
// Kernel C: deterministic mean over B losses -> scalar out
// ---------------------------------------------------------------------------
__global__ void __launch_bounds__(256) mean_kernel(float* __restrict__ out) {
    __shared__ double sh[256];
    int tid = threadIdx.x;
    double s = 0.0;
    #pragma unroll
    for (int i = tid; i < B_DIM; i += 256) s += g_loss[i];
    sh[tid] = s;
    __syncthreads();
    #pragma unroll
    for (int o = 128; o; o >>= 1) {
        if (tid < o) sh[tid] += sh[tid + o];
        __syncthreads();
    }
    if (tid == 0) out[0] = (float)(sh[0] * (1.0 / (double)B_DIM));
}

extern "C" void kernel_launch(void* const* d_in, const int* in_sizes, int n_in,
                              void* d_out, int out_size) {
    const int*   y_true;
    const float* y_pred;
    if (in_sizes[0] == B_DIM * L_DIM) {
        y_true = (const int*)d_in[0];
        y_pred = (const float*)d_in[1];
    } else {
        y_true = (const int*)d_in[1];
        y_pred = (const float*)d_in[0];
    }

    // G: fused logsumexp + gather + normalize. 524288 warps, 8 per block.
    gather_kernel<<<(T_DIM * B_DIM) / 8, 256>>>(y_pred, y_true);
    // B: forward recursion, warp per batch element, cp.async pipelined
    ctc_forward<<<B_DIM / NWARP, 64>>>(y_true);
    // C: mean
    mean_kernel<<<1, 256>>>((float*)d_out);
}

// round 10
// speedup vs baseline: 4.7786x; 4.7786x over previous
#include <cuda_runtime.h>
#include <math.h>

#define T_DIM 512
#define B_DIM 1024
#define V_DIM 96
#define L_DIM 48
#define PKW   50          // packed row: 48 label probs + blank + pad (200 B)
#define CHUNK 16          // timesteps per cp.async chunk (3200 B contiguous)
#define NCH   4           // ring depth (chunks)
#define NCHUNKS (T_DIM / CHUNK)   // 32

// scratch (no cudaMalloc allowed). Layout: g_pk[b][t][PKW] so per-b rows are
// contiguous in t (one chunk = CHUNK*PKW floats = 3200 B, 16 B aligned).
__device__ float  g_pk[(size_t)B_DIM * T_DIM * PKW];   // ~105 MB
__device__ double g_loss[B_DIM];

// ---------------------------------------------------------------------------
// Kernel G: fused logsumexp + gather + normalize.
// One warp per (t,b) row (r = t*B+b). Writes 49 normalized probs to
// g_pk[(b*T + t)*PKW]: float2 (labels 2l,2l+1) per lane<24, blank at +48.
// ---------------------------------------------------------------------------
__global__ void __launch_bounds__(256) gather_kernel(const float* __restrict__ y_pred,
                                                     const int*   __restrict__ y_true) {
    int r    = (blockIdx.x * blockDim.x + threadIdx.x) >> 5;  // row id, grid exact
    int lane = threadIdx.x & 31;
    int t = r >> 10;             // r / B_DIM
    int b = r & (B_DIM - 1);

    const float* row = y_pred + (size_t)r * V_DIM;
    float x0 = row[lane];
    float x1 = row[lane + 32];
    float x2 = row[lane + 64];

    float m = fmaxf(x0, fmaxf(x1, x2));
    #pragma unroll
    for (int o = 16; o; o >>= 1) m = fmaxf(m, __shfl_xor_sync(0xFFFFFFFFu, m, o));
    float s = __expf(x0 - m) + __expf(x1 - m) + __expf(x2 - m);
    #pragma unroll
    for (int o = 16; o; o >>= 1) s += __shfl_xor_sync(0xFFFFFFFFu, s, o);
    float inv = __fdividef(1.0f, s);

    float* out = g_pk + ((size_t)b * T_DIM + t) * PKW;
    if (lane < 24) {
        int2 lp = *(const int2*)(y_true + b * L_DIM + 2 * lane);
        float p0 = __expf(row[lp.x] - m) * inv;   // L1 hits
        float p1 = __expf(row[lp.y] - m) * inv;
        *(float2*)(out + 2 * lane) = make_float2(p0, p1);
    } else if (lane == 24) {
        out[48] = __expf(row[0] - m) * inv;       // blank
    }
}

// ---------------------------------------------------------------------------
// Kernel B: CTC forward recursion, warp per batch element, ALL-FP32 alphas.
// (B300 FP64 throughput is ~18.4 cyc/warp-instr/SM -- the R6-R9 wall.)
// Lane l owns states 4l..4l+3; one __shfl_up per step.
// Range handled by exact power-of-2 rescale every 4 steps: warp max via one
// REDUX.SYNC (__reduce_max_sync on float bits, order-preserving for +floats),
// recentered at 2^110 -> guaranteed >=100-nat window above FTZ at all times.
// Probs arrive via the cp.async smem ring (guaranteed 2-chunk lead).
// ---------------------------------------------------------------------------
#define NWARP 2   // warps (batch elements) per block
__global__ void __launch_bounds__(64) ctc_forward(const int* __restrict__ y_true) {
    __shared__ __align__(16) float ring[NWARP][NCH][CHUNK * PKW];  // 25.6 KB

    const int wib = threadIdx.x >> 5;
    const int b   = blockIdx.x * NWARP + wib;
    const int l   = threadIdx.x & 31;

    // skip-transition predicates
    int lab0 = 0, lab1 = 0;
    if (l < 24) {
        int2 lp = *(const int2*)(y_true + b * L_DIM + 2 * l);
        lab0 = lp.x; lab1 = lp.y;
    }
    int prevlab1 = __shfl_up_sync(0xFFFFFFFFu, lab1, 1);
    const float skip1 = (l >= 1 && l < 24 && lab0 != prevlab1) ? 1.0f : 0.0f;
    const float skip3 = (l < 24 && lab1 != lab0) ? 1.0f : 0.0f;
    const int off2 = (l < 24) ? 2 * l : 0;

    const float* src = g_pk + (size_t)b * T_DIM * PKW;

    // issue one chunk copy: 200 x 16B cp.async, one commit_group
    #define ISSUE(c_)                                                          \
    {                                                                          \
        const float* gsrc = src + (size_t)(c_) * (CHUNK * PKW);                \
        float* sdst = &ring[wib][(c_) & (NCH - 1)][0];                         \
        for (int i = l; i < (CHUNK * PKW) / 4; i += 32) {                      \
            unsigned sa = (unsigned)__cvta_generic_to_shared(sdst + 4 * i);    \
            asm volatile("cp.async.ca.shared.global [%0], [%1], 16;"           \
                         :: "r"(sa), "l"(gsrc + 4 * i));                       \
        }                                                                      \
        asm volatile("cp.async.commit_group;" ::: "memory");                   \
    }

    // prologue: chunks 0..NCH-2 in flight
    ISSUE(0); ISSUE(1); ISSUE(2);

    float a0 = 0.0f, a1 = 0.0f, a2 = 0.0f, a3 = 0.0f;
    int acc_k = 0;   // total power-of-2 shift applied: stored = true * 2^acc_k

    #define STEP(j, p01, pb)                                                   \
    {                                                                          \
        float sh3 = __shfl_up_sync(0xFFFFFFFFu, a3, 1);                        \
        if (l == 0) sh3 = 0.0f;                                                \
        float n0 = (a0 + sh3) * (pb);                                          \
        float n1 = fmaf(skip1, sh3, a0 + a1) * (p01).x;                        \
        float n2 = (a1 + a2) * (pb);                                           \
        float n3 = fmaf(skip3, a1, a2 + a3) * (p01).y;                         \
        if (l >= 24) { n1 = 0.0f; n2 = 0.0f; n3 = 0.0f; }                      \
        if (l >  24) { n0 = 0.0f; }                                            \
        a0 = n0; a1 = n1; a2 = n2; a3 = n3;                                    \
        if (((j) & 3) == 3) {                                                  \
            float v = fmaxf(fmaxf(a0, a1), fmaxf(a2, a3));                     \
            unsigned mb = __reduce_max_sync(0xFFFFFFFFu, __float_as_uint(v));  \
            int eb = (int)(mb >> 23);                                          \
            int shift = (127 + 110) - eb;       /* recenter max at 2^110 */    \
            if (shift >  126) shift =  126;                                    \
            if (shift < -126) shift = -126;                                    \
            float scale = __int_as_float((127 + shift) << 23);                 \
            a0 *= scale; a1 *= scale; a2 *= scale; a3 *= scale;                \
            acc_k += shift;                                                    \
        }                                                                      \
    }

    for (int c = 0; c < NCHUNKS; c++) {
        // wait until chunk c's group has completed (groups retire in order)
        int n = NCHUNKS - 1 - c; if (n > NCH - 2) n = NCH - 2;
        if      (n == 2) asm volatile("cp.async.wait_group 2;" ::: "memory");
        else if (n == 1) asm volatile("cp.async.wait_group 1;" ::: "memory");
        else             asm volatile("cp.async.wait_group 0;" ::: "memory");
        __syncwarp();
        if (c + NCH - 1 < NCHUNKS) ISSUE(c + NCH - 1);

        const float* pk = &ring[wib][c & (NCH - 1)][0];
        #pragma unroll
        for (int j = 0; j < CHUNK; j++) {
            const float* prow = pk + j * PKW;
            float2 p01 = *(const float2*)(prow + off2);
            float  pb  = prow[48];
            if (c == 0 && j == 0) {   // t = 0 init: states 0,1 on lane 0
                if (l == 0) { a0 = pb; a1 = p01.x; }
                continue;
            }
            STEP(j, p01, pb);
        }
        __syncwarp();   // all lanes done reading slot before it is re-issued
    }
    #undef STEP
    #undef ISSUE

    // terminal states: s=95 (lane 23, a3) and s=96 (lane 24, a0)
    float v95 = __shfl_sync(0xFFFFFFFFu, a3, 23);
    float v96 = __shfl_sync(0xFFFFFFFFu, a0, 24);
    if (l == 0) {
        // true_alpha = stored * 2^{-acc_k}; loss = -log(true_alpha)
        g_loss[b] = -log((double)(v95 + v96)) + (double)acc_k * 0.6931471805599453094;
    }
}

// ---------------------------------------------------------------------------
// Kernel C: deterministic mean over B losses -> scalar out
// ---------------------------------------------------------------------------
__global__ void __launch_bounds__(256) mean_kernel(float* __restrict__ out) {
    __shared__ double sh[256];
    int tid = threadIdx.x;
    double s = 0.0;
    #pragma unroll
    for (int i = tid; i < B_DIM; i += 256) s += g_loss[i];
    sh[tid] = s;
    __syncthreads();
    #pragma unroll
    for (int o = 128; o; o >>= 1) {
        if (tid < o) sh[tid] += sh[tid + o];
        __syncthreads();
    }
    if (tid == 0) out[0] = (float)(sh[0] * (1.0 / (double)B_DIM));
}

extern "C" void kernel_launch(void* const* d_in, const int* in_sizes, int n_in,
                              void* d_out, int out_size) {
    const int*   y_true;
    const float* y_pred;
    if (in_sizes[0] == B_DIM * L_DIM) {
        y_true = (const int*)d_in[0];
        y_pred = (const float*)d_in[1];
    } else {
        y_true = (const int*)d_in[1];
        y_pred = (const float*)d_in[0];
    }

    // G: fused logsumexp + gather + normalize. 524288 warps, 8 per block.
    gather_kernel<<<(T_DIM * B_DIM) / 8, 256>>>(y_pred, y_true);
    // B: forward recursion, warp per batch element, all-FP32 + cp.async ring
    ctc_forward<<<B_DIM / NWARP, 64>>>(y_true);
    // C: mean
    mean_kernel<<<1, 256>>>((float*)d_out);
}

// round 11
// speedup vs baseline: 5.8294x; 1.2199x over previous
#include <cuda_runtime.h>
#include <math.h>

#define T_DIM 512
#define B_DIM 1024
#define V_DIM 96
#define L_DIM 48
#define PKW   50          // packed row: 48 label probs + blank + pad (200 B)
#define CHUNK 16          // timesteps per cp.async chunk (3200 B contiguous)
#define NCH   4           // ring depth (chunks)
#define NCHUNKS (T_DIM / CHUNK)   // 32

// scratch (no cudaMalloc allowed). Layout: g_pk[b][t][PKW] so per-b rows are
// contiguous in t (one chunk = CHUNK*PKW floats = 3200 B, 16 B aligned).
__device__ float  g_pk[(size_t)B_DIM * T_DIM * PKW];   // ~105 MB
__device__ double g_loss[B_DIM];

// ---------------------------------------------------------------------------
// Kernel G: fused logsumexp + gather + normalize -- 4 rows per warp.
// Row r = t*B+b handled by an 8-lane subgroup (sub = lane&7):
//   3x LDG.128 per lane (12 elems), 3-step butterfly max/sum over 8 lanes,
//   then each lane gathers 6 labels (int2 x3) and writes 3x float2 of
//   normalized probs; sub==0 writes the blank prob at +48.
// Issue-bound before (~40 warp-instrs/row); this form is ~20/row.
// ---------------------------------------------------------------------------
__global__ void __launch_bounds__(256) gather_kernel(const float* __restrict__ y_pred,
                                                     const int*   __restrict__ y_true) {
    int warp = (blockIdx.x * blockDim.x + threadIdx.x) >> 5;
    int lane = threadIdx.x & 31;
    int g   = lane >> 3, sub = lane & 7;
    int r   = warp * 4 + g;              // grid sized exactly: 4 rows per warp
    int t   = r >> 10;                   // r / B_DIM
    int b   = r & (B_DIM - 1);

    const float* row = y_pred + (size_t)r * V_DIM;
    const float4* rp = (const float4*)row + sub;
    float4 v0 = rp[0];      // elems  4*sub    .. 4*sub+3
    float4 v1 = rp[8];      // elems 32+4*sub  ..
    float4 v2 = rp[16];     // elems 64+4*sub  ..

    float m = fmaxf(fmaxf(fmaxf(v0.x, v0.y), fmaxf(v0.z, v0.w)),
             fmaxf(fmaxf(fmaxf(v1.x, v1.y), fmaxf(v1.z, v1.w)),
                   fmaxf(fmaxf(fmaxf(v2.x, v2.y), fmaxf(v2.z, v2.w)), -1e30f)));
    #pragma unroll
    for (int o = 4; o; o >>= 1) m = fmaxf(m, __shfl_xor_sync(0xFFFFFFFFu, m, o));

    float s = __expf(v0.x - m) + __expf(v0.y - m) + __expf(v0.z - m) + __expf(v0.w - m)
            + __expf(v1.x - m) + __expf(v1.y - m) + __expf(v1.z - m) + __expf(v1.w - m)
            + __expf(v2.x - m) + __expf(v2.y - m) + __expf(v2.z - m) + __expf(v2.w - m);
    #pragma unroll
    for (int o = 4; o; o >>= 1) s += __shfl_xor_sync(0xFFFFFFFFu, s, o);
    float inv = __fdividef(1.0f, s);

    // gather 6 labels for this lane; label reads hit L1 (row just streamed)
    const int* lbase = y_true + b * L_DIM + 6 * sub;
    int2 la = *(const int2*)(lbase);
    int2 lb = *(const int2*)(lbase + 2);
    int2 lc = *(const int2*)(lbase + 4);

    float p0 = __expf(row[la.x] - m) * inv;
    float p1 = __expf(row[la.y] - m) * inv;
    float p2 = __expf(row[lb.x] - m) * inv;
    float p3 = __expf(row[lb.y] - m) * inv;
    float p4 = __expf(row[lc.x] - m) * inv;
    float p5 = __expf(row[lc.y] - m) * inv;

    float* out = g_pk + ((size_t)b * T_DIM + t) * PKW + 6 * sub;
    *(float2*)(out)     = make_float2(p0, p1);
    *(float2*)(out + 2) = make_float2(p2, p3);
    *(float2*)(out + 4) = make_float2(p4, p5);
    if (sub == 0) {
        out[48] = __expf(row[0] - m) * inv;     // blank (offset 48 from row base)
    }
}

// ---------------------------------------------------------------------------
// Kernel B: CTC forward recursion, warp per batch element, ALL-FP32 alphas.
// (B300 FP64 throughput ~18.4 cyc/warp-instr/SM was the R6-R9 wall.)
// Lane l owns states 4l..4l+3; one __shfl_up per step.
// Range: exact power-of-2 rescale every 4 steps via one REDUX.SYNC
// (order-preserving on positive-float bits), recentered at 2^110 ->
// guaranteed >=100-nat window above FTZ at all times.
// Probs arrive via cp.async smem ring (guaranteed 2-chunk lead).
// ---------------------------------------------------------------------------
#define NWARP 2   // warps (batch elements) per block
__global__ void __launch_bounds__(64) ctc_forward(const int* __restrict__ y_true) {
    __shared__ __align__(16) float ring[NWARP][NCH][CHUNK * PKW];  // 25.6 KB

    const int wib = threadIdx.x >> 5;
    const int b   = blockIdx.x * NWARP + wib;
    const int l   = threadIdx.x & 31;

    // skip-transition predicates
    int lab0 = 0, lab1 = 0;
    if (l < 24) {
        int2 lp = *(const int2*)(y_true + b * L_DIM + 2 * l);
        lab0 = lp.x; lab1 = lp.y;
    }
    int prevlab1 = __shfl_up_sync(0xFFFFFFFFu, lab1, 1);
    const float skip1 = (l >= 1 && l < 24 && lab0 != prevlab1) ? 1.0f : 0.0f;
    const float skip3 = (l < 24 && lab1 != lab0) ? 1.0f : 0.0f;
    const int off2 = (l < 24) ? 2 * l : 0;

    const float* src = g_pk + (size_t)b * T_DIM * PKW;

    // issue one chunk copy: 200 x 16B cp.async, one commit_group
    #define ISSUE(c_)                                                          \
    {                                                                          \
        const float* gsrc = src + (size_t)(c_) * (CHUNK * PKW);                \
        float* sdst = &ring[wib][(c_) & (NCH - 1)][0];                         \
        for (int i = l; i < (CHUNK * PKW) / 4; i += 32) {                      \
            unsigned sa = (unsigned)__cvta_generic_to_shared(sdst + 4 * i);    \
            asm volatile("cp.async.ca.shared.global [%0], [%1], 16;"           \
                         :: "r"(sa), "l"(gsrc + 4 * i));                       \
        }                                                                      \
        asm volatile("cp.async.commit_group;" ::: "memory");                   \
    }

    // prologue: chunks 0..NCH-2 in flight
    ISSUE(0); ISSUE(1); ISSUE(2);

    float a0 = 0.0f, a1 = 0.0f, a2 = 0.0f, a3 = 0.0f;
    int acc_k = 0;   // total power-of-2 shift applied: stored = true * 2^acc_k

    #define STEP(j, p01, pb)                                                   \
    {                                                                          \
        float sh3 = __shfl_up_sync(0xFFFFFFFFu, a3, 1);                        \
        if (l == 0) sh3 = 0.0f;                                                \
        float n0 = (a0 + sh3) * (pb);                                          \
        float n1 = fmaf(skip1, sh3, a0 + a1) * (p01).x;                        \
        float n2 = (a1 + a2) * (pb);                                           \
        float n3 = fmaf(skip3, a1, a2 + a3) * (p01).y;                         \
        if (l >= 24) { n1 = 0.0f; n2 = 0.0f; n3 = 0.0f; }                      \
        if (l >  24) { n0 = 0.0f; }                                            \
        a0 = n0; a1 = n1; a2 = n2; a3 = n3;                                    \
        if (((j) & 3) == 3) {                                                  \
            float v = fmaxf(fmaxf(a0, a1), fmaxf(a2, a3));                     \
            unsigned mb = __reduce_max_sync(0xFFFFFFFFu, __float_as_uint(v));  \
            int eb = (int)(mb >> 23);                                          \
            int shift = (127 + 110) - eb;       /* recenter max at 2^110 */    \
            if (shift >  126) shift =  126;                                    \
            if (shift < -126) shift = -126;                                    \
            float scale = __int_as_float((127 + shift) << 23);                 \
            a0 *= scale; a1 *= scale; a2 *= scale; a3 *= scale;                \
            acc_k += shift;                                                    \
        }                                                                      \
    }

    for (int c = 0; c < NCHUNKS; c++) {
        // wait until chunk c's group has completed (groups retire in order)
        int n = NCHUNKS - 1 - c; if (n > NCH - 2) n = NCH - 2;
        if      (n == 2) asm volatile("cp.async.wait_group 2;" ::: "memory");
        else if (n == 1) asm volatile("cp.async.wait_group 1;" ::: "memory");
        else             asm volatile("cp.async.wait_group 0;" ::: "memory");
        __syncwarp();
        if (c + NCH - 1 < NCHUNKS) ISSUE(c + NCH - 1);

        const float* pk = &ring[wib][c & (NCH - 1)][0];
        #pragma unroll
        for (int j = 0; j < CHUNK; j++) {
            const float* prow = pk + j * PKW;
            float2 p01 = *(const float2*)(prow + off2);
            float  pb  = prow[48];
            if (c == 0 && j == 0) {   // t = 0 init: states 0,1 on lane 0
                if (l == 0) { a0 = pb; a1 = p01.x; }
                continue;
            }
            STEP(j, p01, pb);
        }
        __syncwarp();   // all lanes done reading slot before it is re-issued
    }
    #undef STEP
    #undef ISSUE

    // terminal states: s=95 (lane 23, a3) and s=96 (lane 24, a0)
    float v95 = __shfl_sync(0xFFFFFFFFu, a3, 23);
    float v96 = __shfl_sync(0xFFFFFFFFu, a0, 24);
    if (l == 0) {
        // true_alpha = stored * 2^{-acc_k}; loss = -log(true_alpha)
        g_loss[b] = -log((double)(v95 + v96)) + (double)acc_k * 0.6931471805599453094;
    }
}

// ---------------------------------------------------------------------------
// Kernel C: deterministic mean over B losses -> scalar out
// ---------------------------------------------------------------------------
__global__ void __launch_bounds__(256) mean_kernel(float* __restrict__ out) {
    __shared__ double sh[256];
    int tid = threadIdx.x;
    double s = 0.0;
    #pragma unroll
    for (int i = tid; i < B_DIM; i += 256) s += g_loss[i];
    sh[tid] = s;
    __syncthreads();
    #pragma unroll
    for (int o = 128; o; o >>= 1) {
        if (tid < o) sh[tid] += sh[tid + o];
        __syncthreads();
    }
    if (tid == 0) out[0] = (float)(sh[0] * (1.0 / (double)B_DIM));
}

extern "C" void kernel_launch(void* const* d_in, const int* in_sizes, int n_in,
                              void* d_out, int out_size) {
    const int*   y_true;
    const float* y_pred;
    if (in_sizes[0] == B_DIM * L_DIM) {
        y_true = (const int*)d_in[0];
        y_pred = (const float*)d_in[1];
    } else {
        y_true = (const int*)d_in[1];
        y_pred = (const float*)d_in[0];
    }

    // G: fused logsumexp + gather + normalize. 131072 warps x 4 rows, 8/block.
    gather_kernel<<<(T_DIM * B_DIM / 4) / 8, 256>>>(y_pred, y_true);
    // B: forward recursion, warp per batch element, all-FP32 + cp.async ring
    ctc_forward<<<B_DIM / NWARP, 64>>>(y_true);
    // C: mean
    mean_kernel<<<1, 256>>>((float*)d_out);
}

// round 12
// speedup vs baseline: 7.3401x; 1.2592x over previous
#include <cuda_runtime.h>
#include <cuda_fp16.h>
#include <math.h>

#define T_DIM 512
#define B_DIM 1024
#define V_DIM 96
#define L_DIM 48
#define PKW   52          // packed row: 48 label probs + blank + pad (104 B fp16)
#define CHUNK 16          // timesteps per cp.async chunk (1664 B contiguous)
#define NCH   4           // ring depth (chunks)
#define NCHUNKS (T_DIM / CHUNK)   // 32
#define PSCALE_LOG2 5     // stored prob = p * 2^5 (keeps fp16 out of subnormals)

// scratch (no cudaMalloc allowed). Layout: g_pk[b][t][PKW] halves so per-b
// rows are contiguous in t (one chunk = CHUNK*PKW halves = 1664 B, 16B-align).
__device__ __align__(16) __half g_pk[(size_t)B_DIM * T_DIM * PKW];   // ~52 MB
__device__ double g_loss[B_DIM];

// ---------------------------------------------------------------------------
// Kernel G: fused logsumexp + gather + normalize -- 4 rows per warp, fp16 out.
// Row r = t*B+b handled by an 8-lane subgroup (sub = lane&7):
//   3x LDG.128 per lane (12 elems), 3-step butterfly max/sum over 8 lanes,
//   each lane gathers 6 labels and writes 3x half2 of probs scaled by 2^5;
//   sub==0 writes the blank prob at +48.
// ---------------------------------------------------------------------------
__global__ void __launch_bounds__(256) gather_kernel(const float* __restrict__ y_pred,
                                                     const int*   __restrict__ y_true) {
    int warp = (blockIdx.x * blockDim.x + threadIdx.x) >> 5;
    int lane = threadIdx.x & 31;
    int g   = lane >> 3, sub = lane & 7;
    int r   = warp * 4 + g;              // grid sized exactly: 4 rows per warp
    int t   = r >> 10;                   // r / B_DIM
    int b   = r & (B_DIM - 1);

    const float* row = y_pred + (size_t)r * V_DIM;
    const float4* rp = (const float4*)row + sub;
    float4 v0 = rp[0];      // elems  4*sub    .. 4*sub+3
    float4 v1 = rp[8];      // elems 32+4*sub  ..
    float4 v2 = rp[16];     // elems 64+4*sub  ..

    float m = fmaxf(fmaxf(fmaxf(v0.x, v0.y), fmaxf(v0.z, v0.w)),
             fmaxf(fmaxf(fmaxf(v1.x, v1.y), fmaxf(v1.z, v1.w)),
                   fmaxf(fmaxf(v2.x, v2.y), fmaxf(v2.z, v2.w))));
    #pragma unroll
    for (int o = 4; o; o >>= 1) m = fmaxf(m, __shfl_xor_sync(0xFFFFFFFFu, m, o));

    float s = __expf(v0.x - m) + __expf(v0.y - m) + __expf(v0.z - m) + __expf(v0.w - m)
            + __expf(v1.x - m) + __expf(v1.y - m) + __expf(v1.z - m) + __expf(v1.w - m)
            + __expf(v2.x - m) + __expf(v2.y - m) + __expf(v2.z - m) + __expf(v2.w - m);
    #pragma unroll
    for (int o = 4; o; o >>= 1) s += __shfl_xor_sync(0xFFFFFFFFu, s, o);
    float inv = __fdividef((float)(1 << PSCALE_LOG2), s);   // 2^5 / sum

    // gather 6 labels for this lane; label reads hit L1 (row just streamed)
    const int* lbase = y_true + b * L_DIM + 6 * sub;
    int2 la = *(const int2*)(lbase);
    int2 lb = *(const int2*)(lbase + 2);
    int2 lc = *(const int2*)(lbase + 4);

    float p0 = __expf(row[la.x] - m) * inv;
    float p1 = __expf(row[la.y] - m) * inv;
    float p2 = __expf(row[lb.x] - m) * inv;
    float p3 = __expf(row[lb.y] - m) * inv;
    float p4 = __expf(row[lc.x] - m) * inv;
    float p5 = __expf(row[lc.y] - m) * inv;

    __half* out = g_pk + ((size_t)b * T_DIM + t) * PKW + 6 * sub;
    *(__half2*)(out)     = __float22half2_rn(make_float2(p0, p1));
    *(__half2*)(out + 2) = __float22half2_rn(make_float2(p2, p3));
    *(__half2*)(out + 4) = __float22half2_rn(make_float2(p4, p5));
    if (sub == 0) {
        out[48] = __float2half_rn(__expf(row[0] - m) * inv);   // blank
    }
}

// ---------------------------------------------------------------------------
// Kernel B: CTC forward recursion, warp per batch element, ALL-FP32 alphas.
// Lane l owns states 4l..4l+3; one __shfl_up per step.
// Range: exact power-of-2 rescale every 4 steps via one REDUX.SYNC,
// recentered at 2^110. Probs arrive scaled by 2^5 (exact, corrected at end).
// fp16 probs stream in via the cp.async smem ring (guaranteed 2-chunk lead).
// ---------------------------------------------------------------------------
#define NWARP 2   // warps (batch elements) per block
__global__ void __launch_bounds__(64) ctc_forward(const int* __restrict__ y_true) {
    __shared__ __align__(16) __half ring[NWARP][NCH][CHUNK * PKW];  // 13.3 KB

    const int wib = threadIdx.x >> 5;
    const int b   = blockIdx.x * NWARP + wib;
    const int l   = threadIdx.x & 31;

    // skip-transition predicates
    int lab0 = 0, lab1 = 0;
    if (l < 24) {
        int2 lp = *(const int2*)(y_true + b * L_DIM + 2 * l);
        lab0 = lp.x; lab1 = lp.y;
    }
    int prevlab1 = __shfl_up_sync(0xFFFFFFFFu, lab1, 1);
    const float skip1 = (l >= 1 && l < 24 && lab0 != prevlab1) ? 1.0f : 0.0f;
    const float skip3 = (l < 24 && lab1 != lab0) ? 1.0f : 0.0f;
    const int off2 = (l < 24) ? 2 * l : 0;

    const __half* src = g_pk + (size_t)b * T_DIM * PKW;

    // issue one chunk copy: 104 x 16B cp.async, one commit_group
    #define ISSUE(c_)                                                          \
    {                                                                          \
        const __half* gsrc = src + (size_t)(c_) * (CHUNK * PKW);               \
        __half* sdst = &ring[wib][(c_) & (NCH - 1)][0];                        \
        for (int i = l; i < (CHUNK * PKW) / 8; i += 32) {                      \
            unsigned sa = (unsigned)__cvta_generic_to_shared(sdst + 8 * i);    \
            asm volatile("cp.async.ca.shared.global [%0], [%1], 16;"           \
                         :: "r"(sa), "l"(gsrc + 8 * i));                       \
        }                                                                      \
        asm volatile("cp.async.commit_group;" ::: "memory");                   \
    }

    // prologue: chunks 0..NCH-2 in flight
    ISSUE(0); ISSUE(1); ISSUE(2);

    float a0 = 0.0f, a1 = 0.0f, a2 = 0.0f, a3 = 0.0f;
    int acc_k = 0;   // power-of-2 shift: stored = true * 2^{acc_k + 5*steps}

    #define STEP(j, p01f, pb)                                                  \
    {                                                                          \
        float sh3 = __shfl_up_sync(0xFFFFFFFFu, a3, 1);                        \
        if (l == 0) sh3 = 0.0f;                                                \
        float n0 = (a0 + sh3) * (pb);                                          \
        float n1 = fmaf(skip1, sh3, a0 + a1) * (p01f).x;                       \
        float n2 = (a1 + a2) * (pb);                                           \
        float n3 = fmaf(skip3, a1, a2 + a3) * (p01f).y;                        \
        if (l >= 24) { n1 = 0.0f; n2 = 0.0f; n3 = 0.0f; }                      \
        if (l >  24) { n0 = 0.0f; }                                            \
        a0 = n0; a1 = n1; a2 = n2; a3 = n3;                                    \
        if (((j) & 3) == 3) {                                                  \
            float v = fmaxf(fmaxf(a0, a1), fmaxf(a2, a3));                     \
            unsigned mb = __reduce_max_sync(0xFFFFFFFFu, __float_as_uint(v));  \
            int eb = (int)(mb >> 23);                                          \
            int shift = (127 + 110) - eb;       /* recenter max at 2^110 */    \
            if (shift >  126) shift =  126;                                    \
            if (shift < -126) shift = -126;                                    \
            float scale = __int_as_float((127 + shift) << 23);                 \
            a0 *= scale; a1 *= scale; a2 *= scale; a3 *= scale;                \
            acc_k += shift;                                                    \
        }                                                                      \
    }

    for (int c = 0; c < NCHUNKS; c++) {
        // wait until chunk c's group has completed (groups retire in order)
        int n = NCHUNKS - 1 - c; if (n > NCH - 2) n = NCH - 2;
        if      (n == 2) asm volatile("cp.async.wait_group 2;" ::: "memory");
        else if (n == 1) asm volatile("cp.async.wait_group 1;" ::: "memory");
        else             asm volatile("cp.async.wait_group 0;" ::: "memory");
        __syncwarp();
        if (c + NCH - 1 < NCHUNKS) ISSUE(c + NCH - 1);

        const __half* pk = &ring[wib][c & (NCH - 1)][0];
        #pragma unroll
        for (int j = 0; j < CHUNK; j++) {
            const __half* prow = pk + j * PKW;
            float2 p01 = __half22float2(*(const __half2*)(prow + off2));
            float  pb  = __half2float(prow[48]);
            if (c == 0 && j == 0) {   // t = 0 init: states 0,1 on lane 0
                if (l == 0) { a0 = pb; a1 = p01.x; }
                continue;
            }
            STEP(j, p01, pb);
        }
        __syncwarp();   // all lanes done reading slot before it is re-issued
    }
    #undef STEP
    #undef ISSUE

    // terminal states: s=95 (lane 23, a3) and s=96 (lane 24, a0)
    float v95 = __shfl_sync(0xFFFFFFFFu, a3, 23);
    float v96 = __shfl_sync(0xFFFFFFFFu, a0, 24);
    if (l == 0) {
        // stored = true * 2^{acc_k + 5*512}  (512 prob factors incl. t=0 init)
        double kk = (double)acc_k + (double)(PSCALE_LOG2 * T_DIM);
        g_loss[b] = -log((double)(v95 + v96)) + kk * 0.6931471805599453094;
    }
}

// ---------------------------------------------------------------------------
// Kernel C: deterministic mean over B losses -> scalar out
// ---------------------------------------------------------------------------
__global__ void __launch_bounds__(256) mean_kernel(float* __restrict__ out) {
    __shared__ double sh[256];
    int tid = threadIdx.x;
    double s = 0.0;
    #pragma unroll
    for (int i = tid; i < B_DIM; i += 256) s += g_loss[i];
    sh[tid] = s;
    __syncthreads();
    #pragma unroll
    for (int o = 128; o; o >>= 1) {
        if (tid < o) sh[tid] += sh[tid + o];
        __syncthreads();
    }
    if (tid == 0) out[0] = (float)(sh[0] * (1.0 / (double)B_DIM));
}

extern "C" void kernel_launch(void* const* d_in, const int* in_sizes, int n_in,
                              void* d_out, int out_size) {
    const int*   y_true;
    const float* y_pred;
    if (in_sizes[0] == B_DIM * L_DIM) {
        y_true = (const int*)d_in[0];
        y_pred = (const float*)d_in[1];
    } else {
        y_true = (const int*)d_in[1];
        y_pred = (const float*)d_in[0];
    }

    // G: fused logsumexp + gather + normalize (fp16 out). 131072 warps x 4 rows.
    gather_kernel<<<(T_DIM * B_DIM / 4) / 8, 256>>>(y_pred, y_true);
    // B: forward recursion, warp per batch element, fp32 + cp.async fp16 ring
    ctc_forward<<<B_DIM / NWARP, 64>>>(y_true);
    // C: mean
    mean_kernel<<<1, 256>>>((float*)d_out);
}

// round 13
// speedup vs baseline: 7.5768x; 1.0322x over previous
#include <cuda_runtime.h>
#include <cuda_fp16.h>
#include <math.h>

#define T_DIM 512
#define B_DIM 1024
#define V_DIM 96
#define L_DIM 48
#define PKW   52          // packed row: 48 label probs + blank + pad (104 B fp16)
#define CHUNK 16          // timesteps per cp.async chunk (1664 B contiguous)
#define NCH   4           // ring depth (chunks)
#define NCHUNKS (T_DIM / CHUNK)   // 32
#define PSCALE_LOG2 5     // stored prob = p * 2^5 (keeps fp16 out of subnormals)
#define SROW  104         // smem row stride in floats (416 B -> group offsets 32B apart mod 128)

// scratch (no cudaMalloc allowed)
__device__ __align__(16) __half g_pk[(size_t)B_DIM * T_DIM * PKW];   // ~52 MB
__device__ unsigned long long g_acc;      // fixed-point sum of losses (zeroed by G)
__device__ int g_cnt = 0;                 // completion counter (self-resetting)

// ---------------------------------------------------------------------------
// Kernel G: fused logsumexp + gather + normalize -- 4 rows per warp, fp16 out.
// Row r = t*B+b handled by an 8-lane subgroup (sub = lane&7).
// The 12 exps per lane computed for the denominator are staged in SMEM
// (3x STS.128) and the 49 gathers become LDS hits -- this removes the
// ~72 L1 wavefronts/warp of scattered scalar LDGs and 7 MUFU exps/lane.
// Also zeroes the loss accumulator for kernel B (strictly ordered in-stream).
// ---------------------------------------------------------------------------
__global__ void __launch_bounds__(256) gather_kernel(const float* __restrict__ y_pred,
                                                     const int*   __restrict__ y_true) {
    __shared__ float sex[8][4 * SROW];    // 8 warps x 4 rows x 104 floats = 13.3 KB

    if (blockIdx.x == 0 && threadIdx.x == 0) g_acc = 0ull;   // reset for B

    int wib  = threadIdx.x >> 5;
    int warp = (blockIdx.x * blockDim.x + threadIdx.x) >> 5;
    int lane = threadIdx.x & 31;
    int g   = lane >> 3, sub = lane & 7;
    int r   = warp * 4 + g;              // grid sized exactly: 4 rows per warp
    int t   = r >> 10;                   // r / B_DIM
    int b   = r & (B_DIM - 1);

    const float* row = y_pred + (size_t)r * V_DIM;
    const float4* rp = (const float4*)row + sub;
    float4 v0 = rp[0];      // elems  4*sub    .. 4*sub+3
    float4 v1 = rp[8];      // elems 32+4*sub  ..
    float4 v2 = rp[16];     // elems 64+4*sub  ..

    float m = fmaxf(fmaxf(fmaxf(v0.x, v0.y), fmaxf(v0.z, v0.w)),
             fmaxf(fmaxf(fmaxf(v1.x, v1.y), fmaxf(v1.z, v1.w)),
                   fmaxf(fmaxf(v2.x, v2.y), fmaxf(v2.z, v2.w))));
    #pragma unroll
    for (int o = 4; o; o >>= 1) m = fmaxf(m, __shfl_xor_sync(0xFFFFFFFFu, m, o));

    float4 e0 = make_float4(__expf(v0.x - m), __expf(v0.y - m), __expf(v0.z - m), __expf(v0.w - m));
    float4 e1 = make_float4(__expf(v1.x - m), __expf(v1.y - m), __expf(v1.z - m), __expf(v1.w - m));
    float4 e2 = make_float4(__expf(v2.x - m), __expf(v2.y - m), __expf(v2.z - m), __expf(v2.w - m));

    float s = (e0.x + e0.y + e0.z + e0.w)
            + (e1.x + e1.y + e1.z + e1.w)
            + (e2.x + e2.y + e2.z + e2.w);
    #pragma unroll
    for (int o = 4; o; o >>= 1) s += __shfl_xor_sync(0xFFFFFFFFu, s, o);
    float inv = __fdividef((float)(1 << PSCALE_LOG2), s);   // 2^5 / sum

    // stage exps for this row in smem (same elem indices as the loads)
    float* myrow = &sex[wib][g * SROW];
    *(float4*)(myrow + 4 * sub)      = e0;
    *(float4*)(myrow + 32 + 4 * sub) = e1;
    *(float4*)(myrow + 64 + 4 * sub) = e2;
    __syncwarp();

    // gather 6 labels for this lane from smem
    const int* lbase = y_true + b * L_DIM + 6 * sub;
    int2 la = *(const int2*)(lbase);
    int2 lb = *(const int2*)(lbase + 2);
    int2 lc = *(const int2*)(lbase + 4);

    float p0 = myrow[la.x] * inv;
    float p1 = myrow[la.y] * inv;
    float p2 = myrow[lb.x] * inv;
    float p3 = myrow[lb.y] * inv;
    float p4 = myrow[lc.x] * inv;
    float p5 = myrow[lc.y] * inv;

    __half* out = g_pk + ((size_t)b * T_DIM + t) * PKW + 6 * sub;
    *(__half2*)(out)     = __float22half2_rn(make_float2(p0, p1));
    *(__half2*)(out + 2) = __float22half2_rn(make_float2(p2, p3));
    *(__half2*)(out + 4) = __float22half2_rn(make_float2(p4, p5));
    if (sub == 0) {
        out[48] = __float2half_rn(myrow[0] * inv);   // blank = vocab 0
    }
}

// ---------------------------------------------------------------------------
// Kernel B: CTC forward recursion, warp per batch element, ALL-FP32 alphas.
// Lane l owns states 4l..4l+3; one __shfl_up per step.
// Range: exact power-of-2 rescale every 4 steps via REDUX.SYNC, recentered at
// 2^110. Probs arrive x2^5 (exact, corrected at end) via cp.async smem ring.
// Mean is fused here: per-warp loss -> fixed-point (x 2^32) integer atomic
// (associative -> bit-deterministic); last-finishing warp writes d_out.
// ---------------------------------------------------------------------------
#define NWARP 2   // warps (batch elements) per block
__global__ void __launch_bounds__(64) ctc_forward(const int* __restrict__ y_true,
                                                  float* __restrict__ out) {
    __shared__ __align__(16) __half ring[NWARP][NCH][CHUNK * PKW];  // 13.3 KB

    const int wib = threadIdx.x >> 5;
    const int b   = blockIdx.x * NWARP + wib;
    const int l   = threadIdx.x & 31;

    // skip-transition predicates
    int lab0 = 0, lab1 = 0;
    if (l < 24) {
        int2 lp = *(const int2*)(y_true + b * L_DIM + 2 * l);
        lab0 = lp.x; lab1 = lp.y;
    }
    int prevlab1 = __shfl_up_sync(0xFFFFFFFFu, lab1, 1);
    const float skip1 = (l >= 1 && l < 24 && lab0 != prevlab1) ? 1.0f : 0.0f;
    const float skip3 = (l < 24 && lab1 != lab0) ? 1.0f : 0.0f;
    const int off2 = (l < 24) ? 2 * l : 0;

    const __half* src = g_pk + (size_t)b * T_DIM * PKW;

    // issue one chunk copy: 104 x 16B cp.async, one commit_group
    #define ISSUE(c_)                                                          \
    {                                                                          \
        const __half* gsrc = src + (size_t)(c_) * (CHUNK * PKW);               \
        __half* sdst = &ring[wib][(c_) & (NCH - 1)][0];                        \
        for (int i = l; i < (CHUNK * PKW) / 8; i += 32) {                      \
            unsigned sa = (unsigned)__cvta_generic_to_shared(sdst + 8 * i);    \
            asm volatile("cp.async.ca.shared.global [%0], [%1], 16;"           \
                         :: "r"(sa), "l"(gsrc + 8 * i));                       \
        }                                                                      \
        asm volatile("cp.async.commit_group;" ::: "memory");                   \
    }

    // prologue: chunks 0..NCH-2 in flight
    ISSUE(0); ISSUE(1); ISSUE(2);

    float a0 = 0.0f, a1 = 0.0f, a2 = 0.0f, a3 = 0.0f;
    int acc_k = 0;   // power-of-2 shift: stored = true * 2^{acc_k + 5*steps}

    #define STEP(j, p01f, pb)                                                  \
    {                                                                          \
        float sh3 = __shfl_up_sync(0xFFFFFFFFu, a3, 1);                        \
        if (l == 0) sh3 = 0.0f;                                                \
        float n0 = (a0 + sh3) * (pb);                                          \
        float n1 = fmaf(skip1, sh3, a0 + a1) * (p01f).x;                       \
        float n2 = (a1 + a2) * (pb);                                           \
        float n3 = fmaf(skip3, a1, a2 + a3) * (p01f).y;                        \
        if (l >= 24) { n1 = 0.0f; n2 = 0.0f; n3 = 0.0f; }                      \
        if (l >  24) { n0 = 0.0f; }                                            \
        a0 = n0; a1 = n1; a2 = n2; a3 = n3;                                    \
        if (((j) & 3) == 3) {                                                  \
            float v = fmaxf(fmaxf(a0, a1), fmaxf(a2, a3));                     \
            unsigned mb = __reduce_max_sync(0xFFFFFFFFu, __float_as_uint(v));  \
            int eb = (int)(mb >> 23);                                          \
            int shift = (127 + 110) - eb;       /* recenter max at 2^110 */    \
            if (shift >  126) shift =  126;                                    \
            if (shift < -126) shift = -126;                                    \
            float scale = __int_as_float((127 + shift) << 23);                 \
            a0 *= scale; a1 *= scale; a2 *= scale; a3 *= scale;                \
            acc_k += shift;                                                    \
        }                                                                      \
    }

    for (int c = 0; c < NCHUNKS; c++) {
        // wait until chunk c's group has completed (groups retire in order)
        int n = NCHUNKS - 1 - c; if (n > NCH - 2) n = NCH - 2;
        if      (n == 2) asm volatile("cp.async.wait_group 2;" ::: "memory");
        else if (n == 1) asm volatile("cp.async.wait_group 1;" ::: "memory");
        else             asm volatile("cp.async.wait_group 0;" ::: "memory");
        __syncwarp();
        if (c + NCH - 1 < NCHUNKS) ISSUE(c + NCH - 1);

        const __half* pk = &ring[wib][c & (NCH - 1)][0];
        #pragma unroll
        for (int j = 0; j < CHUNK; j++) {
            const __half* prow = pk + j * PKW;
            float2 p01 = __half22float2(*(const __half2*)(prow + off2));
            float  pb  = __half2float(prow[48]);
            if (c == 0 && j == 0) {   // t = 0 init: states 0,1 on lane 0
                if (l == 0) { a0 = pb; a1 = p01.x; }
                continue;
            }
            STEP(j, p01, pb);
        }
        __syncwarp();   // all lanes done reading slot before it is re-issued
    }
    #undef STEP
    #undef ISSUE

    // terminal states: s=95 (lane 23, a3) and s=96 (lane 24, a0)
    float v95 = __shfl_sync(0xFFFFFFFFu, a3, 23);
    float v96 = __shfl_sync(0xFFFFFFFFu, a0, 24);
    if (l == 0) {
        // stored = true * 2^{acc_k + 5*512}  (512 prob factors incl. t=0 init)
        double kk = (double)acc_k + (double)(PSCALE_LOG2 * T_DIM);
        double loss = -log((double)(v95 + v96)) + kk * 0.6931471805599453094;
        // deterministic fused mean: fixed-point (2^32) integer accumulate
        unsigned long long fx = (unsigned long long)(loss * 4294967296.0 + 0.5);
        atomicAdd(&g_acc, fx);
        __threadfence();
        int done = atomicAdd(&g_cnt, 1);
        if (done == B_DIM - 1) {
            g_cnt = 0;   // self-reset for next replay
            unsigned long long tot = atomicAdd(&g_acc, 0ull);
            out[0] = (float)((double)tot * (1.0 / 4294967296.0 / (double)B_DIM));
        }
    }
}

extern "C" void kernel_launch(void* const* d_in, const int* in_sizes, int n_in,
                              void* d_out, int out_size) {
    const int*   y_true;
    const float* y_pred;
    if (in_sizes[0] == B_DIM * L_DIM) {
        y_true = (const int*)d_in[0];
        y_pred = (const float*)d_in[1];
    } else {
        y_true = (const int*)d_in[1];
        y_pred = (const float*)d_in[0];
    }

    // G: fused logsumexp + gather + normalize (fp16 out), smem-staged gathers.
    gather_kernel<<<(T_DIM * B_DIM / 4) / 8, 256>>>(y_pred, y_true);
    // B: forward recursion + fused deterministic mean -> d_out
    ctc_forward<<<B_DIM / NWARP, 64>>>(y_true, (float*)d_out);
}